// round 4
// baseline (speedup 1.0000x reference)
#include <cuda_runtime.h>
#include <math.h>

#define T1V 257
#define BATCH 512
#define SDV 128
#define ADV 32
#define HSV 512
#define SFV 256
#define R2 131072    // 256*512 rows
#define RALL 131584  // 257*512 rows
#define NBLK 256

// ---------------- scratch (__device__ globals; no runtime allocation) ----------------
__device__ float g_feats[(size_t)T1V * BATCH * HSV];   // 257x512x512
__device__ float g_outs [(size_t)T1V * BATCH * SFV];   // 257x512x256
__device__ float g_pred [(size_t)256 * BATCH * SFV];   // 256x512x256
__device__ float g_hidA [(size_t)R2 * HSV];            // 131072x512
__device__ float g_hidB [(size_t)R2 * HSV];            // 131072x512
__device__ float g_h0a  [BATCH * SFV];
__device__ float g_h0b  [BATCH * SFV];
__device__ float g_h1a  [BATCH * SFV];
__device__ float g_h1b  [BATCH * SFV];
__device__ float g_pfl  [2048];
__device__ float g_pil  [512];
__device__ unsigned g_barcnt;
__device__ unsigned g_bargen;

// ---------------- helpers ----------------
__device__ __forceinline__ float sigmoidf_(float x) { return 1.0f / (1.0f + expf(-x)); }

// ---------------- init: zero recurrent state + reset grid barrier ----------------
__global__ void init_kernel() {
    int i = blockIdx.x * blockDim.x + threadIdx.x;  // 131072 total
    g_h0a[i] = 0.f;
    g_h0b[i] = 0.f;
    g_h1a[i] = 0.f;
    g_h1b[i] = 0.f;
    if (i == 0) { g_barcnt = 0u; g_bargen = 0u; }
}

// ---------------- grid-wide barrier (all NBLK CTAs resident) ----------------
__device__ __forceinline__ void gsync(unsigned& gen) {
    __threadfence();
    __syncthreads();
    if (threadIdx.x == 0) {
        unsigned a = atomicAdd(&g_barcnt, 1u);
        if (a == NBLK - 1) {
            g_barcnt = 0u;
            __threadfence();
            atomicExch(&g_bargen, gen + 1u);
        } else {
            while (*((volatile unsigned*)&g_bargen) < gen + 1u) { }
        }
        __threadfence();   // gpu-scope fence -> L1D invalidate before consuming peers' h
    }
    __syncthreads();
    gen += 1u;
}

// ---------------- persistent LSTM scan ----------------
// 256 CTAs: bt = blk>>4 (batch tile of 32), gt = blk&15 (unit tile of 16).
// Per phase: gates tile [32 batch x 16 units x 4 gates], K split in 64-chunks,
// double-buffered smem, register prefetch, 1 syncthreads per chunk.
// smem layout (floats): asb[2][64][36], wsb[2][64][68], msk[32]

__device__ __forceinline__ void ld_chunk(
    const float* __restrict__ A, int AK, const float* __restrict__ W, int ko,
    int b0, int u0, int rA, int rW, int lk,
    float4& av0, float4& av1, float4* wv)
{
    av0 = *(const float4*)(A + (size_t)(b0 + rA) * AK + ko + lk);
    av1 = *(const float4*)(A + (size_t)(b0 + rA + 1) * AK + ko + lk);
#pragma unroll
    for (int j = 0; j < 4; j++) {
        int r = rW + j;
        int grow = ((r & 3) << 8) + u0 + (r >> 2);  // gate*256 + unit
        wv[j] = *(const float4*)(W + (size_t)grow * AK + ko + lk);
    }
}

__device__ __forceinline__ void st_chunk(
    float* __restrict__ asb, float* __restrict__ wsb, const float* __restrict__ msk,
    int buf, int rA, int rW, int lk, int use_mask,
    const float4& av0, const float4& av1, const float4* wv)
{
    float* ab = asb + buf * 2304;
    float* wb = wsb + buf * 4352;
    float m0 = use_mask ? msk[rA] : 1.f;
    float m1 = use_mask ? msk[rA + 1] : 1.f;
    ab[(lk + 0) * 36 + rA] = av0.x * m0;
    ab[(lk + 1) * 36 + rA] = av0.y * m0;
    ab[(lk + 2) * 36 + rA] = av0.z * m0;
    ab[(lk + 3) * 36 + rA] = av0.w * m0;
    ab[(lk + 0) * 36 + rA + 1] = av1.x * m1;
    ab[(lk + 1) * 36 + rA + 1] = av1.y * m1;
    ab[(lk + 2) * 36 + rA + 1] = av1.z * m1;
    ab[(lk + 3) * 36 + rA + 1] = av1.w * m1;
#pragma unroll
    for (int j = 0; j < 4; j++) {
        int r = rW + j;
        wb[(lk + 0) * 68 + r] = wv[j].x;
        wb[(lk + 1) * 68 + r] = wv[j].y;
        wb[(lk + 2) * 68 + r] = wv[j].z;
        wb[(lk + 3) * 68 + r] = wv[j].w;
    }
}

__device__ __forceinline__ void comp_chunk(
    float acc[2][4], const float* __restrict__ asb, const float* __restrict__ wsb,
    int buf, int bi, int ni)
{
    const float* ab = asb + buf * 2304 + (bi << 1);
    const float* wb = wsb + buf * 4352 + (ni << 2);
#pragma unroll
    for (int k = 0; k < 64; k++) {
        float2 a2 = *(const float2*)(ab + k * 36);
        float4 w4 = *(const float4*)(wb + k * 68);
        acc[0][0] += a2.x * w4.x; acc[0][1] += a2.x * w4.y;
        acc[0][2] += a2.x * w4.z; acc[0][3] += a2.x * w4.w;
        acc[1][0] += a2.y * w4.x; acc[1][1] += a2.y * w4.y;
        acc[1][2] += a2.y * w4.z; acc[1][3] += a2.y * w4.w;
    }
}

__device__ __forceinline__ void run_phase(
    float acc[2][4],
    const float* __restrict__ A1, int K1, int m1, const float* __restrict__ W1,
    const float* __restrict__ A2, int K2, int m2, const float* __restrict__ W2,
    int b0, int u0, int bi, int ni, int lk, int rA, int rW,
    float* __restrict__ asb, float* __restrict__ wsb, const float* __restrict__ msk)
{
    const int nc1 = K1 >> 6;
    const int nc = nc1 + (K2 >> 6);
    float4 av0, av1, wv[4];

    ld_chunk(A1, K1, W1, 0, b0, u0, rA, rW, lk, av0, av1, wv);
    st_chunk(asb, wsb, msk, 0, rA, rW, lk, m1, av0, av1, wv);
    __syncthreads();
    for (int c = 0; c < nc; c++) {
        if (c + 1 < nc) {
            int cn = c + 1;
            const float* A; const float* W; int AK, mm, ko;
            if (cn < nc1) { A = A1; W = W1; AK = K1; mm = m1; ko = cn << 6; }
            else          { A = A2; W = W2; AK = K2; mm = m2; ko = (cn - nc1) << 6; }
            ld_chunk(A, AK, W, ko, b0, u0, rA, rW, lk, av0, av1, wv);
            comp_chunk(acc, asb, wsb, c & 1, bi, ni);
            st_chunk(asb, wsb, msk, cn & 1, rA, rW, lk, mm, av0, av1, wv);
            __syncthreads();
        } else {
            comp_chunk(acc, asb, wsb, c & 1, bi, ni);
        }
    }
}

__global__ __launch_bounds__(256, 2) void lstm_scan_kernel(
    const float* __restrict__ feats, const int* __restrict__ dones,
    const float* __restrict__ Wih0, const float* __restrict__ Whh0,
    const float* __restrict__ bih0, const float* __restrict__ bhh0,
    const float* __restrict__ Wih1, const float* __restrict__ Whh1,
    const float* __restrict__ bih1, const float* __restrict__ bhh1,
    float* __restrict__ h0A, float* __restrict__ h0B,
    float* __restrict__ h1A, float* __restrict__ h1B,
    float* __restrict__ outs, float* __restrict__ hid)
{
    extern __shared__ float sh[];
    float* asb = sh;             // 2*64*36 = 4608
    float* wsb = sh + 4608;      // 2*64*68 = 8704
    float* msk = sh + 13312;     // 32

    const int tid = threadIdx.x;
    const int bi = tid >> 4, ni = tid & 15;
    const int lk = ni << 2;
    const int rA = bi << 1, rW = bi << 2;
    const int bt = blockIdx.x >> 4, gt = blockIdx.x & 15;
    const int b0 = bt << 5, u0 = gt << 4;
    const int u = u0 + ni;

    float bs0[4], bs1[4];
#pragma unroll
    for (int g = 0; g < 4; g++) {
        bs0[g] = bih0[(g << 8) + u] + bhh0[(g << 8) + u];
        bs1[g] = bih1[(g << 8) + u] + bhh1[(g << 8) + u];
    }
    float c0r[2] = {0.f, 0.f}, c1r[2] = {0.f, 0.f};
    unsigned gen = 0;

    for (int t = 0; t < 257; t++) {
        const float* h0r = (t & 1) ? h0B : h0A;
        float* h0w = (t & 1) ? h0A : h0B;
        const float* h1r = (t & 1) ? h1B : h1A;
        float* h1w = (t & 1) ? h1A : h1B;

        if (tid < 32) msk[tid] = 1.f - (float)dones[t * BATCH + b0 + tid];

        float acc[2][4];
#pragma unroll
        for (int i = 0; i < 2; i++)
#pragma unroll
            for (int g = 0; g < 4; g++) acc[i][g] = 0.f;

        // ---- layer 0: gates = feats[t] @ Wih0^T + (h0*m) @ Whh0^T
        run_phase(acc, feats + (size_t)t * 262144, 512, 0, Wih0,
                  h0r, 256, 1, Whh0,
                  b0, u0, bi, ni, lk, rA, rW, asb, wsb, msk);
#pragma unroll
        for (int i = 0; i < 2; i++) {
            int b = b0 + rA + i;
            float m = msk[rA + i];
            float ig = sigmoidf_(acc[i][0] + bs0[0]);
            float fg = sigmoidf_(acc[i][1] + bs0[1]);
            float gg = tanhf(acc[i][2] + bs0[2]);
            float og = sigmoidf_(acc[i][3] + bs0[3]);
            float c2 = fg * (c0r[i] * m) + ig * gg;
            float h2 = og * tanhf(c2);
            c0r[i] = c2;
            h0w[(size_t)b * SFV + u] = h2;
            if (t == 256) { hid[b * SFV + u] = h2; hid[262144 + b * SFV + u] = c2; }
        }
        gsync(gen);

        // ---- layer 1: gates = h0' @ Wih1^T + (h1*m) @ Whh1^T
#pragma unroll
        for (int i = 0; i < 2; i++)
#pragma unroll
            for (int g = 0; g < 4; g++) acc[i][g] = 0.f;
        run_phase(acc, h0w, 256, 0, Wih1,
                  h1r, 256, 1, Whh1,
                  b0, u0, bi, ni, lk, rA, rW, asb, wsb, msk);
#pragma unroll
        for (int i = 0; i < 2; i++) {
            int b = b0 + rA + i;
            float m = msk[rA + i];
            float ig = sigmoidf_(acc[i][0] + bs1[0]);
            float fg = sigmoidf_(acc[i][1] + bs1[1]);
            float gg = tanhf(acc[i][2] + bs1[2]);
            float og = sigmoidf_(acc[i][3] + bs1[3]);
            float c2 = fg * (c1r[i] * m) + ig * gg;
            float h2 = og * tanhf(c2);
            c1r[i] = c2;
            h1w[(size_t)b * SFV + u] = h2;
            outs[(size_t)t * 131072 + b * SFV + u] = h2;
            if (t == 256) { hid[131072 + b * SFV + u] = h2; hid[393216 + b * SFV + u] = c2; }
        }
        gsync(gen);
    }
}

// ---------------- generic SGEMM: C = act(A @ W^T + bias) ----------------
#define KC 16
template <int ACT>
__global__ __launch_bounds__(256) void gemm_kernel(
    const float* __restrict__ A1, int K1,
    const float* __restrict__ A2,
    const float* __restrict__ W,
    const float* __restrict__ bias,
    float* __restrict__ C,
    int M, int N, int K)
{
    __shared__ float as_[KC][132];
    __shared__ float bs_[KC][132];
    const int m0 = blockIdx.x * 128;
    const int n0 = blockIdx.y * 128;
    const int tid = threadIdx.x;
    const int mi = tid >> 4;
    const int ni = tid & 15;
    const int lrow = tid >> 2;
    const int lk = (tid & 3) * 4;

    float acc[8][8];
#pragma unroll
    for (int i = 0; i < 8; i++)
#pragma unroll
        for (int j = 0; j < 8; j++) acc[i][j] = 0.f;

    for (int kc = 0; kc < K; kc += KC) {
        const float* Asrc;
        int Ak, koff;
        if (kc < K1) { Asrc = A1; Ak = K1; koff = kc; }
        else         { Asrc = A2; Ak = K - K1; koff = kc - K1; }
#pragma unroll
        for (int r = 0; r < 2; r++) {
            int row = lrow + r * 64;
            float4 v = *(const float4*)(Asrc + (size_t)(m0 + row) * Ak + koff + lk);
            as_[lk + 0][row] = v.x; as_[lk + 1][row] = v.y;
            as_[lk + 2][row] = v.z; as_[lk + 3][row] = v.w;
            float4 w = *(const float4*)(W + (size_t)(n0 + row) * K + kc + lk);
            bs_[lk + 0][row] = w.x; bs_[lk + 1][row] = w.y;
            bs_[lk + 2][row] = w.z; bs_[lk + 3][row] = w.w;
        }
        __syncthreads();
#pragma unroll
        for (int k = 0; k < KC; k++) {
            float4 a0 = *(const float4*)&as_[k][mi * 8];
            float4 a1 = *(const float4*)&as_[k][mi * 8 + 4];
            float a[8] = {a0.x, a0.y, a0.z, a0.w, a1.x, a1.y, a1.z, a1.w};
            float b[8];
#pragma unroll
            for (int j = 0; j < 8; j++) b[j] = bs_[k][ni + j * 16];
#pragma unroll
            for (int i = 0; i < 8; i++)
#pragma unroll
                for (int j = 0; j < 8; j++) acc[i][j] += a[i] * b[j];
        }
        __syncthreads();
    }
#pragma unroll
    for (int i = 0; i < 8; i++) {
        int row = m0 + mi * 8 + i;
#pragma unroll
        for (int j = 0; j < 8; j++) {
            int col = n0 + ni + j * 16;
            float v = acc[i][j] + bias[col];
            if (ACT == 1) v = fmaxf(v, 0.f);
            C[(size_t)row * N + col] = v;
        }
    }
}

// ---------------- forward loss + intrinsic reward ----------------
__global__ void floss_kernel(const float* __restrict__ pred, const float* __restrict__ outs,
                             float* __restrict__ intr, float* __restrict__ pfl)
{
    const int w = threadIdx.x >> 5, lane = threadIdx.x & 31;
    const int r0 = blockIdx.x * 64;
    __shared__ float sred[8];
    float wacc = 0.f;
    for (int p = 0; p < 8; p++) {
        int r = r0 + p * 8 + w;
        const float4* pp = (const float4*)(pred + (size_t)r * SFV) + lane * 2;
        const float4* np = (const float4*)(outs + (size_t)(r + BATCH) * SFV) + lane * 2;
        float4 p0 = pp[0], p1 = pp[1], n0 = np[0], n1 = np[1];
        float d0 = p0.x - n0.x, d1 = p0.y - n0.y, d2 = p0.z - n0.z, d3 = p0.w - n0.w;
        float d4 = p1.x - n1.x, d5 = p1.y - n1.y, d6 = p1.z - n1.z, d7 = p1.w - n1.w;
        float s = d0 * d0 + d1 * d1 + d2 * d2 + d3 * d3 + d4 * d4 + d5 * d5 + d6 * d6 + d7 * d7;
#pragma unroll
        for (int o = 16; o; o >>= 1) s += __shfl_xor_sync(0xffffffffu, s, o);
        if (lane == 0) { intr[r] = s; wacc += s; }
    }
    if (lane == 0) sred[w] = wacc;
    __syncthreads();
    if (threadIdx.x == 0) {
        float t = 0.f;
        for (int i = 0; i < 8; i++) t += sred[i];
        pfl[blockIdx.x] = t;
    }
}

// ---------------- inverse head: mu/std + NLL partials ----------------
__global__ void inv_kernel(const float* __restrict__ hm, const float* __restrict__ hs,
                           const float* __restrict__ Wm2, const float* __restrict__ bm2,
                           const float* __restrict__ Ws2, const float* __restrict__ bs2,
                           const float* __restrict__ act, float* __restrict__ pil)
{
    extern __shared__ float sh[];
    float* wm = sh;
    float* ws2s = sh + 16384;
    float* bm = sh + 32768;
    float* bs = sh + 32800;
    float* red = sh + 32832;
    const int tid = threadIdx.x;
    for (int idx = tid; idx < 16384; idx += 256) {
        int d = idx & 31, k = idx >> 5;
        wm[idx] = Wm2[(size_t)d * HSV + k];
        ws2s[idx] = Ws2[(size_t)d * HSV + k];
    }
    if (tid < 32) { bm[tid] = bm2[tid]; bs[tid] = bs2[tid]; }
    __syncthreads();

    const int w = tid >> 5, lane = tid & 31;
    const int r0 = blockIdx.x * 256;
    float ilacc = 0.f;
    for (int p = 0; p < 32; p++) {
        int r = r0 + p * 8 + w;
        const float4* h4m = (const float4*)(hm + (size_t)r * HSV);
        const float4* h4s = (const float4*)(hs + (size_t)r * HSV);
        float am = 0.f, as2 = 0.f;
#pragma unroll 4
        for (int k4 = 0; k4 < 128; k4++) {
            float4 a = h4m[k4];
            float4 b = h4s[k4];
            int kb = k4 * 128 + lane;
            am  += a.x * wm[kb] + a.y * wm[kb + 32] + a.z * wm[kb + 64] + a.w * wm[kb + 96];
            as2 += b.x * ws2s[kb] + b.y * ws2s[kb + 32] + b.z * ws2s[kb + 64] + b.w * ws2s[kb + 96];
        }
        float mu = tanhf(am + bm[lane]);
        float sv = as2 + bs[lane];
        float sd = fmaxf(sv, 0.f) + log1pf(expf(-fabsf(sv)));
        float a_ = act[(size_t)r * ADV + lane];
        float z = (a_ - mu) / sd;
        ilacc += 0.5f * z * z + logf(sd) + 0.91893853320467274f;
    }
#pragma unroll
    for (int o = 16; o; o >>= 1) ilacc += __shfl_xor_sync(0xffffffffu, ilacc, o);
    if (lane == 0) red[w] = ilacc;
    __syncthreads();
    if (tid == 0) {
        float t = 0.f;
        for (int i = 0; i < 8; i++) t += red[i];
        pil[blockIdx.x] = t;
    }
}

// ---------------- final scalar reduce ----------------
__global__ void final_reduce_kernel(const float* __restrict__ pfl, const float* __restrict__ pil,
                                    float* __restrict__ out)
{
    __shared__ float s1[256], s2[256];
    int tid = threadIdx.x;
    float a = 0.f, b = 0.f;
    for (int i = tid; i < 2048; i += 256) a += pfl[i];
    for (int i = tid; i < 512; i += 256) b += pil[i];
    s1[tid] = a; s2[tid] = b;
    __syncthreads();
    for (int st = 128; st; st >>= 1) {
        if (tid < st) { s1[tid] += s1[tid + st]; s2[tid] += s2[tid + st]; }
        __syncthreads();
    }
    if (tid == 0) {
        out[0] = s1[0] / 33554432.f;
        out[1] = s2[0] / 4194304.f;
    }
}

// ---------------- host orchestration ----------------
extern "C" void kernel_launch(void* const* d_in, const int* in_sizes, int n_in,
                              void* d_out, int out_size)
{
    (void)in_sizes; (void)n_in; (void)out_size;
    const float* states = (const float*)d_in[0];
    const float* action = (const float*)d_in[1];
    const int*   dones  = (const int*)d_in[2];
    const float* Wfe = (const float*)d_in[3];
    const float* bfe = (const float*)d_in[4];
    const float* Wih0 = (const float*)d_in[5];
    const float* Whh0 = (const float*)d_in[6];
    const float* bih0 = (const float*)d_in[7];
    const float* bhh0 = (const float*)d_in[8];
    const float* Wih1 = (const float*)d_in[9];
    const float* Whh1 = (const float*)d_in[10];
    const float* bih1 = (const float*)d_in[11];
    const float* bhh1 = (const float*)d_in[12];
    const float* Wf1 = (const float*)d_in[13];
    const float* bf1 = (const float*)d_in[14];
    const float* Wf2 = (const float*)d_in[15];
    const float* bf2 = (const float*)d_in[16];
    const float* Wm1 = (const float*)d_in[17];
    const float* bm1 = (const float*)d_in[18];
    const float* Wm2 = (const float*)d_in[19];
    const float* bm2 = (const float*)d_in[20];
    const float* Ws1 = (const float*)d_in[21];
    const float* bs1 = (const float*)d_in[22];
    const float* Ws2 = (const float*)d_in[23];
    const float* bs2 = (const float*)d_in[24];
    float* out = (float*)d_out;

    float *feats, *outs, *pred, *hidA, *hidB, *h0a, *h0b, *h1a, *h1b, *pfl, *pil;
    cudaGetSymbolAddress((void**)&feats, g_feats);
    cudaGetSymbolAddress((void**)&outs, g_outs);
    cudaGetSymbolAddress((void**)&pred, g_pred);
    cudaGetSymbolAddress((void**)&hidA, g_hidA);
    cudaGetSymbolAddress((void**)&hidB, g_hidB);
    cudaGetSymbolAddress((void**)&h0a, g_h0a);
    cudaGetSymbolAddress((void**)&h0b, g_h0b);
    cudaGetSymbolAddress((void**)&h1a, g_h1a);
    cudaGetSymbolAddress((void**)&h1b, g_h1b);
    cudaGetSymbolAddress((void**)&pfl, g_pfl);
    cudaGetSymbolAddress((void**)&pil, g_pil);

    cudaFuncSetAttribute(inv_kernel, cudaFuncAttributeMaxDynamicSharedMemorySize, 32840 * 4);
    cudaFuncSetAttribute(lstm_scan_kernel, cudaFuncAttributeMaxDynamicSharedMemorySize, 13344 * 4);

    // init recurrent state + grid barrier
    init_kernel<<<256, 512>>>();

    // feature encoder: feats = relu(states @ Wfe^T + bfe)
    gemm_kernel<1><<<dim3(RALL / 128, HSV / 128), 256>>>(
        states, SDV, nullptr, Wfe, bfe, feats, RALL, HSV, SDV);

    // persistent LSTM scan (writes outs + hidden part of out)
    lstm_scan_kernel<<<NBLK, 256, 13344 * 4>>>(
        feats, dones, Wih0, Whh0, bih0, bhh0, Wih1, Whh1, bih1, bhh1,
        h0a, h0b, h1a, h1b, outs, out + 2 + 131072);

    // forward model
    gemm_kernel<1><<<dim3(R2 / 128, HSV / 128), 256>>>(
        outs, SFV, action, Wf1, bf1, hidA, R2, HSV, SFV + ADV);
    gemm_kernel<0><<<dim3(R2 / 128, SFV / 128), 256>>>(
        hidA, HSV, nullptr, Wf2, bf2, pred, R2, SFV, HSV);

    // forward loss + intrinsic reward
    floss_kernel<<<2048, 256>>>(pred, outs, out + 2, pfl);

    // inverse model hiddens
    gemm_kernel<1><<<dim3(R2 / 128, HSV / 128), 256>>>(
        outs, SFV, pred, Wm1, bm1, hidA, R2, HSV, 2 * SFV);
    gemm_kernel<1><<<dim3(R2 / 128, HSV / 128), 256>>>(
        outs, SFV, pred, Ws1, bs1, hidB, R2, HSV, 2 * SFV);

    // mu/std + inverse-loss partials
    inv_kernel<<<512, 256, 32840 * 4>>>(hidA, hidB, Wm2, bm2, Ws2, bs2, action, pil);

    // scalars
    final_reduce_kernel<<<1, 256>>>(pfl, pil, out);
}

// round 5
// speedup vs baseline: 1.2995x; 1.2995x over previous
#include <cuda_runtime.h>
#include <math.h>

#define T1V 257
#define BATCH 512
#define SDV 128
#define ADV 32
#define HSV 512
#define SFV 256
#define R2 131072    // 256*512 rows
#define RALL 131584  // 257*512 rows

// ---------------- scratch (__device__ globals; no runtime allocation) ----------------
__device__ float g_feats[(size_t)T1V * BATCH * HSV];   // 257x512x512
__device__ float g_xw   [(size_t)RALL * 1024];         // feats@Wih0^T + bih0 (257x512x1024)
__device__ float g_outs [(size_t)T1V * BATCH * SFV];   // 257x512x256
__device__ float g_pred [(size_t)256 * BATCH * SFV];   // 256x512x256
__device__ float g_hidA [(size_t)R2 * HSV];            // 131072x512
__device__ float g_hidB [(size_t)R2 * HSV];            // 131072x512
__device__ float g_h0a  [BATCH * SFV];
__device__ float g_h0b  [BATCH * SFV];
__device__ float g_h1a  [BATCH * SFV];
__device__ float g_h1b  [BATCH * SFV];
__device__ float g_c0   [BATCH * SFV];
__device__ float g_c1   [BATCH * SFV];
__device__ float g_pfl  [2048];
__device__ float g_pil  [512];

__device__ __forceinline__ float sigmoidf_(float x) { return 1.0f / (1.0f + expf(-x)); }

// ---------------- init: zero recurrent state ----------------
__global__ void init_kernel() {
    int i = blockIdx.x * blockDim.x + threadIdx.x;  // 131072 total
    g_h0a[i] = 0.f; g_h0b[i] = 0.f;
    g_h1a[i] = 0.f; g_h1b[i] = 0.f;
    g_c0[i] = 0.f;  g_c1[i] = 0.f;
}

// ---------------- LSTM step kernel (one layer, recurrent GEMM + fused gate epilogue) ----
// Output tile: 64 batch x 64 gate-cols (= 16 units x 4 gates, col = uoff*4 + gate).
// 256 threads = 4 K-split groups x 64 threads; each group: 8x8 microtile over its K range.
// smem: per-kgroup double-buffered A(16x68)+W(16x68); red tile 64x68; mask 64.
// NCH = K-chunks (of 16) per kgroup. HASXW: add precomputed input-side gates.
template<int NCH, bool HASXW>
__global__ __launch_bounds__(256, 1) void lstm_step2(
    const float* __restrict__ A1, const float* __restrict__ A2,
    const float* __restrict__ W1, const float* __restrict__ W2,
    const float* __restrict__ xw,
    const float* __restrict__ b1, const float* __restrict__ b2,
    float* __restrict__ cst, float* __restrict__ h_out,
    const int* __restrict__ done,
    float* __restrict__ outs_t,
    float* __restrict__ hid_h, float* __restrict__ hid_c)
{
    extern __shared__ float sh[];
    float* red = sh + 17408;   // 64x68
    float* msk = sh + 21760;   // 64
    const int tid = threadIdx.x;
    const int kg = tid >> 6, kt = tid & 63;
    const int b0 = blockIdx.x << 6, u0 = blockIdx.y << 4;

    // kgroup source selection
    const float* As; const float* Ws; int koff; bool um;
    if (HASXW) { As = A1; Ws = W1; koff = kg << 6; um = true; }        // K=256, 4x64
    else {
        As = (kg < 2) ? A1 : A2; Ws = (kg < 2) ? W1 : W2;              // K=2x256, 4x128
        koff = (kg & 1) << 7; um = (kg >= 2);
    }
    const float* Arow = As + (size_t)(b0 + kt) * SFV + koff;
    const int wrow = ((kt & 3) << 8) + u0 + (kt >> 2);                  // gate*256 + unit
    const float* Wrow = Ws + (size_t)wrow * SFV + koff;
    float* myb = sh + kg * 4352;   // [2 bufs][A:1088 | W:1088]

    if (tid < 64) msk[tid] = 1.f - (float)done[b0 + tid];

    float acc[8][8];
#pragma unroll
    for (int i = 0; i < 8; i++)
#pragma unroll
        for (int j = 0; j < 8; j++) acc[i][j] = 0.f;

    float4 av[4], wv[4];
    const int mi = kt >> 3, ni = kt & 7;

#define LDCH(ch) { int kidx = (ch) << 4; \
    av[0] = *(const float4*)(Arow + kidx);      av[1] = *(const float4*)(Arow + kidx + 4); \
    av[2] = *(const float4*)(Arow + kidx + 8);  av[3] = *(const float4*)(Arow + kidx + 12); \
    wv[0] = *(const float4*)(Wrow + kidx);      wv[1] = *(const float4*)(Wrow + kidx + 4); \
    wv[2] = *(const float4*)(Wrow + kidx + 8);  wv[3] = *(const float4*)(Wrow + kidx + 12); }

#define STCH(buf) { float* ab = myb + (buf) * 2176; float* wb = ab + 1088; \
    float m_ = um ? msk[kt] : 1.f; \
    const float* avf = (const float*)av; const float* wvf = (const float*)wv; \
    _Pragma("unroll") \
    for (int e = 0; e < 16; e++) { ab[e * 68 + kt] = avf[e] * m_; wb[e * 68 + kt] = wvf[e]; } }

#define CPCH(buf) { const float* ab = myb + (buf) * 2176 + (mi << 3); \
    const float* wb = myb + (buf) * 2176 + 1088 + (ni << 3); \
    _Pragma("unroll") \
    for (int k = 0; k < 16; k++) { \
        float4 a0 = *(const float4*)(ab + k * 68); \
        float4 a1 = *(const float4*)(ab + k * 68 + 4); \
        float4 w0 = *(const float4*)(wb + k * 68); \
        float4 w1 = *(const float4*)(wb + k * 68 + 4); \
        float aa[8] = {a0.x, a0.y, a0.z, a0.w, a1.x, a1.y, a1.z, a1.w}; \
        float ww[8] = {w0.x, w0.y, w0.z, w0.w, w1.x, w1.y, w1.z, w1.w}; \
        _Pragma("unroll") \
        for (int i = 0; i < 8; i++) \
        _Pragma("unroll") \
        for (int j = 0; j < 8; j++) acc[i][j] += aa[i] * ww[j]; } }

    LDCH(0);
    __syncthreads();   // msk visible before STCH
    STCH(0);
    __syncthreads();
#pragma unroll
    for (int ch = 0; ch < NCH; ch++) {
        if (ch + 1 < NCH) {
            LDCH(ch + 1);
            CPCH(ch & 1);
            STCH((ch + 1) & 1);
            __syncthreads();
        } else {
            CPCH(ch & 1);
        }
    }

    // in-CTA split-K reduction: kg1..3 -> kg0
#pragma unroll
    for (int g = 1; g < 4; g++) {
        __syncthreads();
        if (kg == g) {
#pragma unroll
            for (int i = 0; i < 8; i++) {
                *(float4*)(red + (mi * 8 + i) * 68 + ni * 8)     = make_float4(acc[i][0], acc[i][1], acc[i][2], acc[i][3]);
                *(float4*)(red + (mi * 8 + i) * 68 + ni * 8 + 4) = make_float4(acc[i][4], acc[i][5], acc[i][6], acc[i][7]);
            }
        }
        __syncthreads();
        if (kg == 0) {
#pragma unroll
            for (int i = 0; i < 8; i++) {
                float4 r0 = *(const float4*)(red + (mi * 8 + i) * 68 + ni * 8);
                float4 r1 = *(const float4*)(red + (mi * 8 + i) * 68 + ni * 8 + 4);
                acc[i][0] += r0.x; acc[i][1] += r0.y; acc[i][2] += r0.z; acc[i][3] += r0.w;
                acc[i][4] += r1.x; acc[i][5] += r1.y; acc[i][6] += r1.z; acc[i][7] += r1.w;
            }
        }
    }
    __syncthreads();
    if (kg == 0) {
#pragma unroll
        for (int i = 0; i < 8; i++) {
            *(float4*)(red + (mi * 8 + i) * 68 + ni * 8)     = make_float4(acc[i][0], acc[i][1], acc[i][2], acc[i][3]);
            *(float4*)(red + (mi * 8 + i) * 68 + ni * 8 + 4) = make_float4(acc[i][4], acc[i][5], acc[i][6], acc[i][7]);
        }
    }
    __syncthreads();

    // fused gate epilogue: 1024 cells (64b x 16u), 4 per thread
    const int ul = tid & 15;
    const int u = u0 + ul;
    float bb[4];
#pragma unroll
    for (int g = 0; g < 4; g++) bb[g] = b1[(g << 8) + u] + (b2 ? b2[(g << 8) + u] : 0.f);
#pragma unroll
    for (int q = 0; q < 4; q++) {
        int bl = (q << 4) + (tid >> 4);
        int b = b0 + bl;
        float4 pre = *(const float4*)(red + bl * 68 + (ul << 2));
        float x0 = 0.f, x1 = 0.f, x2 = 0.f, x3 = 0.f;
        if (HASXW) {
            const float* xr = xw + (size_t)b * 1024 + u;
            x0 = xr[0]; x1 = xr[256]; x2 = xr[512]; x3 = xr[768];
        }
        float ig = sigmoidf_(pre.x + bb[0] + x0);
        float fg = sigmoidf_(pre.y + bb[1] + x1);
        float gg = tanhf(pre.z + bb[2] + x2);
        float og = sigmoidf_(pre.w + bb[3] + x3);
        float m = msk[bl];
        int idx = b * SFV + u;
        float c2 = fg * (cst[idx] * m) + ig * gg;
        float h2 = og * tanhf(c2);
        cst[idx] = c2;
        h_out[idx] = h2;
        if (outs_t) outs_t[idx] = h2;
        if (hid_h) { hid_h[idx] = h2; hid_c[idx] = c2; }
    }
#undef LDCH
#undef STCH
#undef CPCH
}

// ---------------- generic SGEMM: C = act(A @ W^T + bias) ----------------
#define KC 16
template <int ACT>
__global__ __launch_bounds__(256) void gemm_kernel(
    const float* __restrict__ A1, int K1,
    const float* __restrict__ A2,
    const float* __restrict__ W,
    const float* __restrict__ bias,
    float* __restrict__ C,
    int M, int N, int K)
{
    __shared__ float as_[KC][132];
    __shared__ float bs_[KC][132];
    const int m0 = blockIdx.x * 128;
    const int n0 = blockIdx.y * 128;
    const int tid = threadIdx.x;
    const int mi = tid >> 4;
    const int ni = tid & 15;
    const int lrow = tid >> 2;
    const int lk = (tid & 3) * 4;

    float acc[8][8];
#pragma unroll
    for (int i = 0; i < 8; i++)
#pragma unroll
        for (int j = 0; j < 8; j++) acc[i][j] = 0.f;

    for (int kc = 0; kc < K; kc += KC) {
        const float* Asrc;
        int Ak, koff;
        if (kc < K1) { Asrc = A1; Ak = K1; koff = kc; }
        else         { Asrc = A2; Ak = K - K1; koff = kc - K1; }
#pragma unroll
        for (int r = 0; r < 2; r++) {
            int row = lrow + r * 64;
            float4 v = *(const float4*)(Asrc + (size_t)(m0 + row) * Ak + koff + lk);
            as_[lk + 0][row] = v.x; as_[lk + 1][row] = v.y;
            as_[lk + 2][row] = v.z; as_[lk + 3][row] = v.w;
            float4 w = *(const float4*)(W + (size_t)(n0 + row) * K + kc + lk);
            bs_[lk + 0][row] = w.x; bs_[lk + 1][row] = w.y;
            bs_[lk + 2][row] = w.z; bs_[lk + 3][row] = w.w;
        }
        __syncthreads();
#pragma unroll
        for (int k = 0; k < KC; k++) {
            float4 a0 = *(const float4*)&as_[k][mi * 8];
            float4 a1 = *(const float4*)&as_[k][mi * 8 + 4];
            float a[8] = {a0.x, a0.y, a0.z, a0.w, a1.x, a1.y, a1.z, a1.w};
            float b[8];
#pragma unroll
            for (int j = 0; j < 8; j++) b[j] = bs_[k][ni + j * 16];
#pragma unroll
            for (int i = 0; i < 8; i++)
#pragma unroll
                for (int j = 0; j < 8; j++) acc[i][j] += a[i] * b[j];
        }
        __syncthreads();
    }
#pragma unroll
    for (int i = 0; i < 8; i++) {
        int row = m0 + mi * 8 + i;
#pragma unroll
        for (int j = 0; j < 8; j++) {
            int col = n0 + ni + j * 16;
            float v = acc[i][j] + bias[col];
            if (ACT == 1) v = fmaxf(v, 0.f);
            C[(size_t)row * N + col] = v;
        }
    }
}

// ---------------- forward loss + intrinsic reward ----------------
__global__ void floss_kernel(const float* __restrict__ pred, const float* __restrict__ outs,
                             float* __restrict__ intr, float* __restrict__ pfl)
{
    const int w = threadIdx.x >> 5, lane = threadIdx.x & 31;
    const int r0 = blockIdx.x * 64;
    __shared__ float sred[8];
    float wacc = 0.f;
    for (int p = 0; p < 8; p++) {
        int r = r0 + p * 8 + w;
        const float4* pp = (const float4*)(pred + (size_t)r * SFV) + lane * 2;
        const float4* np = (const float4*)(outs + (size_t)(r + BATCH) * SFV) + lane * 2;
        float4 p0 = pp[0], p1 = pp[1], n0 = np[0], n1 = np[1];
        float d0 = p0.x - n0.x, d1 = p0.y - n0.y, d2 = p0.z - n0.z, d3 = p0.w - n0.w;
        float d4 = p1.x - n1.x, d5 = p1.y - n1.y, d6 = p1.z - n1.z, d7 = p1.w - n1.w;
        float s = d0 * d0 + d1 * d1 + d2 * d2 + d3 * d3 + d4 * d4 + d5 * d5 + d6 * d6 + d7 * d7;
#pragma unroll
        for (int o = 16; o; o >>= 1) s += __shfl_xor_sync(0xffffffffu, s, o);
        if (lane == 0) { intr[r] = s; wacc += s; }
    }
    if (lane == 0) sred[w] = wacc;
    __syncthreads();
    if (threadIdx.x == 0) {
        float t = 0.f;
        for (int i = 0; i < 8; i++) t += sred[i];
        pfl[blockIdx.x] = t;
    }
}

// ---------------- inverse head: mu/std + NLL partials ----------------
__global__ void inv_kernel(const float* __restrict__ hm, const float* __restrict__ hs,
                           const float* __restrict__ Wm2, const float* __restrict__ bm2,
                           const float* __restrict__ Ws2, const float* __restrict__ bs2,
                           const float* __restrict__ act, float* __restrict__ pil)
{
    extern __shared__ float sh[];
    float* wm = sh;
    float* ws2s = sh + 16384;
    float* bm = sh + 32768;
    float* bs = sh + 32800;
    float* red = sh + 32832;
    const int tid = threadIdx.x;
    for (int idx = tid; idx < 16384; idx += 256) {
        int d = idx & 31, k = idx >> 5;
        wm[idx] = Wm2[(size_t)d * HSV + k];
        ws2s[idx] = Ws2[(size_t)d * HSV + k];
    }
    if (tid < 32) { bm[tid] = bm2[tid]; bs[tid] = bs2[tid]; }
    __syncthreads();

    const int w = tid >> 5, lane = tid & 31;
    const int r0 = blockIdx.x * 256;
    float ilacc = 0.f;
    for (int p = 0; p < 32; p++) {
        int r = r0 + p * 8 + w;
        const float4* h4m = (const float4*)(hm + (size_t)r * HSV);
        const float4* h4s = (const float4*)(hs + (size_t)r * HSV);
        float am = 0.f, as2 = 0.f;
#pragma unroll 4
        for (int k4 = 0; k4 < 128; k4++) {
            float4 a = h4m[k4];
            float4 b = h4s[k4];
            int kb = k4 * 128 + lane;
            am  += a.x * wm[kb] + a.y * wm[kb + 32] + a.z * wm[kb + 64] + a.w * wm[kb + 96];
            as2 += b.x * ws2s[kb] + b.y * ws2s[kb + 32] + b.z * ws2s[kb + 64] + b.w * ws2s[kb + 96];
        }
        float mu = tanhf(am + bm[lane]);
        float sv = as2 + bs[lane];
        float sd = fmaxf(sv, 0.f) + log1pf(expf(-fabsf(sv)));
        float a_ = act[(size_t)r * ADV + lane];
        float z = (a_ - mu) / sd;
        ilacc += 0.5f * z * z + logf(sd) + 0.91893853320467274f;
    }
#pragma unroll
    for (int o = 16; o; o >>= 1) ilacc += __shfl_xor_sync(0xffffffffu, ilacc, o);
    if (lane == 0) red[w] = ilacc;
    __syncthreads();
    if (tid == 0) {
        float t = 0.f;
        for (int i = 0; i < 8; i++) t += red[i];
        pil[blockIdx.x] = t;
    }
}

// ---------------- final scalar reduce ----------------
__global__ void final_reduce_kernel(const float* __restrict__ pfl, const float* __restrict__ pil,
                                    float* __restrict__ out)
{
    __shared__ float s1[256], s2[256];
    int tid = threadIdx.x;
    float a = 0.f, b = 0.f;
    for (int i = tid; i < 2048; i += 256) a += pfl[i];
    for (int i = tid; i < 512; i += 256) b += pil[i];
    s1[tid] = a; s2[tid] = b;
    __syncthreads();
    for (int st = 128; st; st >>= 1) {
        if (tid < st) { s1[tid] += s1[tid + st]; s2[tid] += s2[tid + st]; }
        __syncthreads();
    }
    if (tid == 0) {
        out[0] = s1[0] / 33554432.f;
        out[1] = s2[0] / 4194304.f;
    }
}

// ---------------- host orchestration ----------------
extern "C" void kernel_launch(void* const* d_in, const int* in_sizes, int n_in,
                              void* d_out, int out_size)
{
    (void)in_sizes; (void)n_in; (void)out_size;
    const float* states = (const float*)d_in[0];
    const float* action = (const float*)d_in[1];
    const int*   dones  = (const int*)d_in[2];
    const float* Wfe = (const float*)d_in[3];
    const float* bfe = (const float*)d_in[4];
    const float* Wih0 = (const float*)d_in[5];
    const float* Whh0 = (const float*)d_in[6];
    const float* bih0 = (const float*)d_in[7];
    const float* bhh0 = (const float*)d_in[8];
    const float* Wih1 = (const float*)d_in[9];
    const float* Whh1 = (const float*)d_in[10];
    const float* bih1 = (const float*)d_in[11];
    const float* bhh1 = (const float*)d_in[12];
    const float* Wf1 = (const float*)d_in[13];
    const float* bf1 = (const float*)d_in[14];
    const float* Wf2 = (const float*)d_in[15];
    const float* bf2 = (const float*)d_in[16];
    const float* Wm1 = (const float*)d_in[17];
    const float* bm1 = (const float*)d_in[18];
    const float* Wm2 = (const float*)d_in[19];
    const float* bm2 = (const float*)d_in[20];
    const float* Ws1 = (const float*)d_in[21];
    const float* bs1 = (const float*)d_in[22];
    const float* Ws2 = (const float*)d_in[23];
    const float* bs2 = (const float*)d_in[24];
    float* out = (float*)d_out;

    float *feats, *xw, *outs, *pred, *hidA, *hidB, *h0a, *h0b, *h1a, *h1b, *c0, *c1, *pfl, *pil;
    cudaGetSymbolAddress((void**)&feats, g_feats);
    cudaGetSymbolAddress((void**)&xw, g_xw);
    cudaGetSymbolAddress((void**)&outs, g_outs);
    cudaGetSymbolAddress((void**)&pred, g_pred);
    cudaGetSymbolAddress((void**)&hidA, g_hidA);
    cudaGetSymbolAddress((void**)&hidB, g_hidB);
    cudaGetSymbolAddress((void**)&h0a, g_h0a);
    cudaGetSymbolAddress((void**)&h0b, g_h0b);
    cudaGetSymbolAddress((void**)&h1a, g_h1a);
    cudaGetSymbolAddress((void**)&h1b, g_h1b);
    cudaGetSymbolAddress((void**)&c0, g_c0);
    cudaGetSymbolAddress((void**)&c1, g_c1);
    cudaGetSymbolAddress((void**)&pfl, g_pfl);
    cudaGetSymbolAddress((void**)&pil, g_pil);

    cudaFuncSetAttribute(inv_kernel, cudaFuncAttributeMaxDynamicSharedMemorySize, 32840 * 4);
    cudaFuncSetAttribute(lstm_step2<4, true>,  cudaFuncAttributeMaxDynamicSharedMemorySize, 21824 * 4);
    cudaFuncSetAttribute(lstm_step2<8, false>, cudaFuncAttributeMaxDynamicSharedMemorySize, 21824 * 4);

    // init recurrent state
    init_kernel<<<256, 512>>>();

    // feature encoder: feats = relu(states @ Wfe^T + bfe)
    gemm_kernel<1><<<dim3(RALL / 128, HSV / 128), 256>>>(
        states, SDV, nullptr, Wfe, bfe, feats, RALL, HSV, SDV);

    // hoisted layer-0 input gates: xw = feats @ Wih0^T + bih0  (all 257 steps at once)
    gemm_kernel<0><<<dim3(RALL / 128, 1024 / 128), 256>>>(
        feats, HSV, nullptr, Wih0, bih0, xw, RALL, 1024, HSV);

    // LSTM scan: 2 small launches per step
    float* hid = out + 2 + 131072;
    dim3 lgrid(8, 16);
    const int smemB = 21824 * 4;
    for (int t = 0; t < T1V; t++) {
        const float* h0r = (t & 1) ? h0b : h0a;  float* h0w = (t & 1) ? h0a : h0b;
        const float* h1r = (t & 1) ? h1b : h1a;  float* h1w = (t & 1) ? h1a : h1b;
        bool last = (t == T1V - 1);
        lstm_step2<4, true><<<lgrid, 256, smemB>>>(
            h0r, nullptr, Whh0, nullptr,
            xw + (size_t)t * 524288,
            bhh0, nullptr,
            c0, h0w, dones + (size_t)t * BATCH,
            nullptr,
            last ? hid : nullptr, last ? hid + 262144 : nullptr);
        lstm_step2<8, false><<<lgrid, 256, smemB>>>(
            h0w, h1r, Wih1, Whh1,
            nullptr,
            bih1, bhh1,
            c1, h1w, dones + (size_t)t * BATCH,
            outs + (size_t)t * 131072,
            last ? hid + 131072 : nullptr, last ? hid + 393216 : nullptr);
    }

    // forward model
    gemm_kernel<1><<<dim3(R2 / 128, HSV / 128), 256>>>(
        outs, SFV, action, Wf1, bf1, hidA, R2, HSV, SFV + ADV);
    gemm_kernel<0><<<dim3(R2 / 128, SFV / 128), 256>>>(
        hidA, HSV, nullptr, Wf2, bf2, pred, R2, SFV, HSV);

    // forward loss + intrinsic reward
    floss_kernel<<<2048, 256>>>(pred, outs, out + 2, pfl);

    // inverse model hiddens
    gemm_kernel<1><<<dim3(R2 / 128, HSV / 128), 256>>>(
        outs, SFV, pred, Wm1, bm1, hidA, R2, HSV, 2 * SFV);
    gemm_kernel<1><<<dim3(R2 / 128, HSV / 128), 256>>>(
        outs, SFV, pred, Ws1, bs1, hidB, R2, HSV, 2 * SFV);

    // mu/std + inverse-loss partials
    inv_kernel<<<512, 256, 32840 * 4>>>(hidA, hidB, Wm2, bm2, Ws2, bs2, action, pil);

    // scalars
    final_reduce_kernel<<<1, 256>>>(pfl, pil, out);
}